// round 16
// baseline (speedup 1.0000x reference)
#include <cuda_runtime.h>
#include <cuda_bf16.h>
#include <math.h>
#include <stdint.h>

#define NB   2048
#define SQN  64
#define PCN  24
#define FDIM 16
#define HDIM 128
#define DDIM 256
#define TDIM 128
#define ADIM 4672
#define APAD 4736
#define E_ADJ 420
#define E_OCC 24
#define E_ATT 40
#define E_DEF 40
#define E_REV 24
#define T512 512
#define NSQT 1024
#define NPCT 384
#define PCSEC (NPCT * 16384)

__device__ float g_shared[NB * DDIM];
__device__ float g_pt[NB * TDIM];
__device__ float g_vt[NB * TDIM];
__device__ float g_hsq[NB * SQN * HDIM];
__device__ float g_rawsq[NB * SQN * HDIM];       // rawAdj -> aggsq -> h2sq
__device__ float g_hpc[NB * PCN * HDIM];
__device__ float g_rawpc[3 * NB * PCN * HDIM];   // att|def|rev raws; sec0 -> h2pc
__device__ float g_pocc[NB * PCN * HDIM];
__device__ __nv_bfloat16 g_Wimg[7 * 2 * 16384];  // fragment-ordered: [img][hi|lo]
__device__ __nv_bfloat16 g_Wph[37 * 2 * 16384];  // policy tiles, fragment-ordered

__device__ __forceinline__ float gelu_f(float x) {
    float u = 0.7978845608028654f * x + 0.0356774081f * x * x * x;
    float au = fabsf(u);
    float e = __expf(-2.0f * au);
    float t = __fdividef(1.0f - e, 1.0f + e);
    t = copysignf(t, u);
    return 0.5f * x * (1.0f + t);
}
__device__ __forceinline__ float sel4(float4 v, int kk) {
    return kk == 0 ? v.x : kk == 1 ? v.y : kk == 2 ? v.z : v.w;
}
__device__ __forceinline__ void mma_bf16(float c[4], uint32_t a0, uint32_t a1,
                                         uint32_t a2, uint32_t a3,
                                         uint32_t b0, uint32_t b1) {
    asm volatile(
        "mma.sync.aligned.m16n8k16.row.col.f32.bf16.bf16.f32 "
        "{%0,%1,%2,%3}, {%4,%5,%6,%7}, {%8,%9}, {%0,%1,%2,%3};"
        : "+f"(c[0]), "+f"(c[1]), "+f"(c[2]), "+f"(c[3])
        : "r"(a0), "r"(a1), "r"(a2), "r"(a3), "r"(b0), "r"(b1));
}

// fragment-image bf16 offset for element (n, k) of a 128x128 B tile
__device__ __forceinline__ int bfrag_off(int n, int k) {
    int j = n >> 3, g = n & 7, jp = j >> 1, jodd = j & 1;
    int kk = k >> 4, q = k & 15;
    int tg = (q >> 1) & 3, regk = q >> 3, lobit = q & 1;
    int u32idx = ((kk * 8 + jp) * 32 + g * 4 + tg) * 4 + jodd * 2 + regk;
    return u32idx * 2 + lobit;
}

// ---------------- HMMA tile machinery (128x128xK=128, 256 thr) ----------------
#define PADK 136
#define TILEB (128 * PADK * 2)
#define BFRAGB 32768
#define TILE_SMEM (2 * TILEB + 2 * BFRAGB)
#define SCRP 132

// linear copy of fragment-ordered B image (hi 32KB + lo 32KB)
__device__ __forceinline__ void stage_Bfrag(uint32_t* Bh, uint32_t* Bl,
                                            const __nv_bfloat16* src, int t) {
    const uint4* sH = (const uint4*)src;
    const uint4* sL = sH + 2048;
    uint4* dH = (uint4*)Bh;
    uint4* dL = (uint4*)Bl;
    #pragma unroll
    for (int i = 0; i < 8; i++) {
        dH[t + i * 256] = sH[t + i * 256];
        dL[t + i * 256] = sL[t + i * 256];
    }
}
__device__ __forceinline__ void stage_Asrc(__nv_bfloat16* Ahi, __nv_bfloat16* Alo,
                                           const float* __restrict__ Asrc, int t) {
    #pragma unroll
    for (int i = 0; i < 16; i++) {
        int e = t + i * 256;
        int r = e >> 5, k0 = (e & 31) * 4;
        float4 v = *(const float4*)&Asrc[r * 128 + k0];
        __nv_bfloat162 h0 = __floats2bfloat162_rn(v.x, v.y);
        __nv_bfloat162 h1 = __floats2bfloat162_rn(v.z, v.w);
        __nv_bfloat162 l0 = __floats2bfloat162_rn(v.x - __bfloat162float(h0.x),
                                                  v.y - __bfloat162float(h0.y));
        __nv_bfloat162 l1 = __floats2bfloat162_rn(v.z - __bfloat162float(h1.x),
                                                  v.w - __bfloat162float(h1.y));
        int o = r * PADK + k0;
        *(uint2*)&Ahi[o] = make_uint2(*(uint32_t*)&h0, *(uint32_t*)&h1);
        *(uint2*)&Alo[o] = make_uint2(*(uint32_t*)&l0, *(uint32_t*)&l1);
    }
}
__device__ __forceinline__ void mma_3pass(float c[16][4],
                                          const __nv_bfloat16* Ahi, const __nv_bfloat16* Alo,
                                          const uint32_t* Bhi, const uint32_t* Blo,
                                          int wid, int g, int tg, int lane) {
    const int ra = wid * 16 + g;
    #pragma unroll
    for (int p = 0; p < 3; p++) {
        const __nv_bfloat16* As = (p == 2) ? Alo : Ahi;
        const uint4* Bf = (const uint4*)((p == 1) ? Blo : Bhi);
        for (int kk = 0; kk < 8; kk++) {
            const int kb = kk * 16 + tg * 2;
            uint32_t a0 = *(const uint32_t*)&As[ra * PADK + kb];
            uint32_t a1 = *(const uint32_t*)&As[(ra + 8) * PADK + kb];
            uint32_t a2 = *(const uint32_t*)&As[ra * PADK + kb + 8];
            uint32_t a3 = *(const uint32_t*)&As[(ra + 8) * PADK + kb + 8];
            const uint4* bp = Bf + kk * 256 + lane;
            #pragma unroll
            for (int jp = 0; jp < 8; jp++) {
                uint4 b = bp[jp * 32];
                mma_bf16(c[2 * jp],     a0, a1, a2, a3, b.x, b.y);
                mma_bf16(c[2 * jp + 1], a0, a1, a2, a3, b.z, b.w);
            }
        }
    }
}

// ============================================================================
// prep: fragment-ordered bf16 hi/lo weight images (7 GNN + 37 policy tiles)
// ============================================================================
__global__ void __launch_bounds__(256) prep_kernel(
    const float* __restrict__ W_adj, const float* __restrict__ W_occ,
    const float* __restrict__ W_att, const float* __restrict__ W_def,
    const float* __restrict__ W_rev, const float* __restrict__ W_out,
    const float* __restrict__ W_ph)
{
    const float* Ws[5] = {W_adj, W_occ, W_att, W_def, W_rev};
    int tid = blockIdx.x * 256 + threadIdx.x;
    int stride = gridDim.x * 256;
    for (int i = tid; i < NB * DDIM; i += stride) g_shared[i] = 0.f;
    for (int i = tid; i < 7 * 16384; i += stride) {
        int idx = i >> 14, n = (i >> 7) & 127, k = i & 127;
        float v = (idx < 5) ? Ws[idx][k * 128 + n] : W_out[k * 256 + (idx - 5) * 128 + n];
        __nv_bfloat16 hi = __float2bfloat16(v);
        __nv_bfloat16 lo = __float2bfloat16(v - __bfloat162float(hi));
        int fo = bfrag_off(n, k);
        g_Wimg[idx * 32768 + fo] = hi;
        g_Wimg[idx * 32768 + 16384 + fo] = lo;
    }
    for (int i = tid; i < 37 * 16384; i += stride) {
        int nt = i >> 14, nl = (i >> 7) & 127, k = i & 127;
        int n = nt * 128 + nl;
        float v = (n < ADIM) ? W_ph[k * ADIM + n] : 0.f;
        __nv_bfloat16 hi = __float2bfloat16(v);
        __nv_bfloat16 lo = __float2bfloat16(v - __bfloat162float(hi));
        int fo = bfrag_off(nl, k);
        g_Wph[nt * 32768 + fo] = hi;
        g_Wph[nt * 32768 + 16384 + fo] = lo;
    }
}

// ============================================================================
// stage1: per board — input GEMM + gelu + edge aggregation
// ============================================================================
#define S1_HSQ  0
#define S1_HPC  8192
#define S1_RADJ 11264
#define S1_RATT 19456
#define S1_RDEF 22528
#define S1_RREV 25600
#define S1_XS   28672
#define S1_XP   29696
#define S1_WI1  30080
#define S1_WI2  32128
#define S1_EIDX 34176
#define S1_BYTES ((34176 + 524) * 4)

__global__ void __launch_bounds__(T512, 1) stage1_kernel(
    const float* __restrict__ x_sq, const float* __restrict__ x_pc,
    const float* __restrict__ W_in_sq, const float* __restrict__ b_in_sq,
    const float* __restrict__ W_in_pc, const float* __restrict__ b_in_pc,
    const int* __restrict__ ei_adj, const int* __restrict__ ei_att,
    const int* __restrict__ ei_def, const int* __restrict__ ei_rev)
{
    extern __shared__ float sm[];
    float* h_sq = sm + S1_HSQ;
    float* h_pc = sm + S1_HPC;
    float* rawAdj = sm + S1_RADJ;
    float* rawAtt = sm + S1_RATT;
    float* rawDef = sm + S1_RDEF;
    float* rawRev = sm + S1_RREV;
    int* eidx = (int*)(sm + S1_EIDX);
    const int b = blockIdx.x;
    const int t = threadIdx.x;

    {
        const int ba = b * E_ADJ;
        for (int i = t; i < E_ADJ; i += T512) {
            int s = ei_adj[ba + i] - b * SQN;
            int d = ei_adj[NB * E_ADJ + ba + i] - b * SQN;
            eidx[i] = s | (d << 8);
        }
        const int bt = b * E_ATT;
        for (int i = t; i < E_ATT; i += T512) {
            int s = ei_att[bt + i] - b * PCN;
            int d = ei_att[NB * E_ATT + bt + i] - b * PCN;
            eidx[E_ADJ + i] = s | (d << 8);
            int s2 = ei_def[bt + i] - b * PCN;
            int d2 = ei_def[NB * E_DEF + bt + i] - b * PCN;
            eidx[E_ADJ + E_ATT + i] = s2 | (d2 << 8);
        }
        const int bo = b * E_REV;
        for (int i = t; i < E_REV; i += T512) {
            int s = ei_rev[bo + i] - b * SQN;
            int d = ei_rev[NB * E_REV + bo + i] - b * PCN;
            eidx[500 + i] = s | (d << 8);
        }
    }
    {
        float4* r4 = (float4*)rawAdj;
        for (int i = t; i < 4352; i += T512) r4[i] = make_float4(0.f, 0.f, 0.f, 0.f);
    }
    {
        float* xs = sm + S1_XS; float* xp = sm + S1_XP;
        float* wi1 = sm + S1_WI1; float* wi2 = sm + S1_WI2;
        for (int i = t; i < SQN * FDIM; i += T512) xs[i] = x_sq[b * SQN * FDIM + i];
        for (int i = t; i < PCN * FDIM; i += T512) xp[i] = x_pc[b * PCN * FDIM + i];
        for (int i = t; i < FDIM * HDIM; i += T512) { wi1[i] = W_in_sq[i]; wi2[i] = W_in_pc[i]; }
    }
    __syncthreads();
    {
        const float* xs = sm + S1_XS; const float* xp = sm + S1_XP;
        const float* wi1 = sm + S1_WI1; const float* wi2 = sm + S1_WI2;
        const int c = t & 127, q = t >> 7;
        float wcol[16];
        #pragma unroll
        for (int k = 0; k < 16; k++) wcol[k] = wi1[k * 128 + c];
        float bias = b_in_sq[c];
        for (int r = q * 16; r < q * 16 + 16; r++) {
            float acc = bias;
            #pragma unroll
            for (int k = 0; k < 16; k++) acc += xs[r * 16 + k] * wcol[k];
            h_sq[r * 128 + c] = gelu_f(acc);
        }
        #pragma unroll
        for (int k = 0; k < 16; k++) wcol[k] = wi2[k * 128 + c];
        bias = b_in_pc[c];
        for (int r = q * 6; r < q * 6 + 6; r++) {
            float acc = bias;
            #pragma unroll
            for (int k = 0; k < 16; k++) acc += xp[r * 16 + k] * wcol[k];
            h_pc[r * 128 + c] = gelu_f(acc);
        }
    }
    __syncthreads();
    {
        const int g = t >> 7, c = t & 127;
        for (int i = g; i < E_ADJ; i += 4) {
            int e = eidx[i];
            atomicAdd(&rawAdj[(e >> 8) * 128 + c], h_sq[(e & 255) * 128 + c]);
        }
        for (int i = g; i < E_ATT; i += 4) {
            int e = eidx[E_ADJ + i];
            atomicAdd(&rawAtt[(e >> 8) * 128 + c], h_pc[(e & 255) * 128 + c]);
        }
        for (int i = g; i < E_DEF; i += 4) {
            int e = eidx[E_ADJ + E_ATT + i];
            atomicAdd(&rawDef[(e >> 8) * 128 + c], h_pc[(e & 255) * 128 + c]);
        }
        for (int i = g; i < E_REV; i += 4) {
            int e = eidx[500 + i];
            atomicAdd(&rawRev[(e >> 8) * 128 + c], h_sq[(e & 255) * 128 + c]);
        }
    }
    __syncthreads();
    {
        float4* d1 = (float4*)(g_hsq + (size_t)b * 8192);
        float4* d2 = (float4*)(g_rawsq + (size_t)b * 8192);
        const float4* s1 = (const float4*)h_sq;
        const float4* s2 = (const float4*)rawAdj;
        #pragma unroll
        for (int i = 0; i < 4; i++) { d1[t + i * T512] = s1[t + i * T512]; d2[t + i * T512] = s2[t + i * T512]; }
        float4* dh = (float4*)(g_hpc + (size_t)b * 3072);
        const float4* sh = (const float4*)h_pc;
        float4* da = (float4*)(g_rawpc + (size_t)b * 3072);
        float4* dd = (float4*)(g_rawpc + (size_t)PCSEC + (size_t)b * 3072);
        float4* dr = (float4*)(g_rawpc + (size_t)2 * PCSEC + (size_t)b * 3072);
        const float4* sa = (const float4*)rawAtt;
        const float4* sd = (const float4*)rawDef;
        const float4* sr = (const float4*)rawRev;
        for (int i = t; i < 768; i += T512) { dh[i] = sh[i]; da[i] = sa[i]; dd[i] = sd[i]; dr[i] = sr[i]; }
    }
}

// ============================================================================
// gemmA: pc-agg (fused h2pc epilogue) first, then pocc, then sq-agg
// ============================================================================
__global__ void __launch_bounds__(256, 1) gemmA_kernel() {
    extern __shared__ uint8_t smraw[];
    __nv_bfloat16* Ahi = (__nv_bfloat16*)(smraw);
    __nv_bfloat16* Alo = (__nv_bfloat16*)(smraw + TILEB);
    uint32_t* Bhi = (uint32_t*)(smraw + 2 * TILEB);
    uint32_t* Blo = (uint32_t*)(smraw + 2 * TILEB + BFRAGB);
    const int t = threadIdx.x;
    const int lane = t & 31, wid = t >> 5;
    const int g = lane >> 2, tg = lane & 3;
    const int bx = blockIdx.x;

    float c[16][4];
    #pragma unroll
    for (int j = 0; j < 16; j++)
        #pragma unroll
        for (int q = 0; q < 4; q++) c[j][q] = 0.f;

    if (bx < NPCT) {
        const int mt = bx;
        #pragma unroll
        for (int s = 0; s < 3; s++) {
            __syncthreads();
            stage_Bfrag(Bhi, Blo, g_Wimg + (2 + s) * 32768, t);
            stage_Asrc(Ahi, Alo, g_rawpc + (size_t)s * PCSEC + (size_t)mt * 16384, t);
            __syncthreads();
            mma_3pass(c, Ahi, Alo, Bhi, Blo, wid, g, tg, lane);
        }
        float* out = g_rawpc + (size_t)mt * 16384;
        const float* hp = g_hpc + (size_t)mt * 16384;
        __syncthreads();
        #pragma unroll
        for (int j = 0; j < 16; j++) {
            int col = j * 8 + tg * 2;
            int r0 = wid * 16 + g;
            float2 h0 = *(const float2*)&hp[r0 * 128 + col];
            float2 h1 = *(const float2*)&hp[(r0 + 8) * 128 + col];
            *(float2*)&out[r0 * 128 + col] =
                make_float2(gelu_f(h0.x + c[j][0]), gelu_f(h0.y + c[j][1]));
            *(float2*)&out[(r0 + 8) * 128 + col] =
                make_float2(gelu_f(h1.x + c[j][2]), gelu_f(h1.y + c[j][3]));
        }
    } else {
        float* out;
        if (bx < 2 * NPCT) {
            const int mt = bx - NPCT;
            stage_Bfrag(Bhi, Blo, g_Wimg + 1 * 32768, t);
            stage_Asrc(Ahi, Alo, g_hpc + (size_t)mt * 16384, t);
            out = g_pocc + (size_t)mt * 16384;
        } else {
            const int mt = bx - 2 * NPCT;
            stage_Bfrag(Bhi, Blo, g_Wimg, t);
            stage_Asrc(Ahi, Alo, g_rawsq + (size_t)mt * 16384, t);
            out = g_rawsq + (size_t)mt * 16384;
        }
        __syncthreads();
        mma_3pass(c, Ahi, Alo, Bhi, Blo, wid, g, tg, lane);
        __syncthreads();
        #pragma unroll
        for (int j = 0; j < 16; j++) {
            int col = j * 8 + tg * 2;
            int r0 = wid * 16 + g;
            *(float2*)&out[r0 * 128 + col] = make_float2(c[j][0], c[j][1]);
            *(float2*)&out[(r0 + 8) * 128 + col] = make_float2(c[j][2], c[j][3]);
        }
    }
}

// ============================================================================
// stage2: sq only — agg = rawsq + occ-scatter(pocc); h2sq = gelu(hsq+agg)
// ============================================================================
__global__ void __launch_bounds__(T512) stage2_kernel(const int* __restrict__ ei_occ) {
    __shared__ float agg[SQN * HDIM];
    const int b = blockIdx.x;
    const int t = threadIdx.x;
    float4* a4 = (float4*)agg;
    const float4* s4 = (const float4*)(g_rawsq + (size_t)b * 8192);
    #pragma unroll
    for (int i = 0; i < 4; i++) a4[t + i * T512] = s4[t + i * T512];
    __syncthreads();
    {
        const int g = t >> 7, c = t & 127;
        for (int i = g; i < E_OCC; i += 4) {
            int sp = ei_occ[b * E_OCC + i] - b * PCN;
            int d  = ei_occ[NB * E_OCC + b * E_OCC + i] - b * SQN;
            atomicAdd(&agg[d * 128 + c], g_pocc[((size_t)b * PCN + sp) * 128 + c]);
        }
    }
    __syncthreads();
    const float4* h4 = (const float4*)(g_hsq + (size_t)b * 8192);
    float4* o4 = (float4*)(g_rawsq + (size_t)b * 8192);
    #pragma unroll
    for (int i = 0; i < 4; i++) {
        int idx = t + i * T512;
        float4 h = h4[idx];
        float4 a = a4[idx];
        float4 o;
        o.x = gelu_f(h.x + a.x); o.y = gelu_f(h.y + a.y);
        o.z = gelu_f(h.z + a.z); o.w = gelu_f(h.w + a.w);
        o4[idx] = o;
    }
}

// ============================================================================
// outgemm: D = h2 @ W_out[nh]; parallel board-mean epilogue
// ============================================================================
__global__ void __launch_bounds__(256, 1) outgemm_kernel(const float* __restrict__ b_out) {
    extern __shared__ uint8_t smraw[];
    __nv_bfloat16* Ahi = (__nv_bfloat16*)(smraw);
    __nv_bfloat16* Alo = (__nv_bfloat16*)(smraw + TILEB);
    uint32_t* Bhi = (uint32_t*)(smraw + 2 * TILEB);
    uint32_t* Blo = (uint32_t*)(smraw + 2 * TILEB + BFRAGB);
    const int t = threadIdx.x;
    const int lane = t & 31, wid = t >> 5;
    const int g = lane >> 2, tg = lane & 3;
    const int mt = blockIdx.x >> 1;
    const int nh = blockIdx.x & 1;
    const bool is_sq = mt < NSQT;
    const float* Asrc = is_sq ? (g_rawsq + (size_t)mt * 16384)
                              : (g_rawpc + (size_t)(mt - NSQT) * 16384);

    stage_Bfrag(Bhi, Blo, g_Wimg + (5 + nh) * 32768, t);
    stage_Asrc(Ahi, Alo, Asrc, t);
    __syncthreads();

    float c[16][4];
    #pragma unroll
    for (int j = 0; j < 16; j++)
        #pragma unroll
        for (int q = 0; q < 4; q++) c[j][q] = 0.f;
    mma_3pass(c, Ahi, Alo, Bhi, Blo, wid, g, tg, lane);
    __syncthreads();

    float* scr = (float*)smraw;
    #pragma unroll
    for (int j = 0; j < 16; j++) {
        int col = j * 8 + tg * 2;
        float bo0 = b_out[nh * 128 + col];
        float bo1 = b_out[nh * 128 + col + 1];
        scr[(wid * 16 + g) * SCRP + col]         = gelu_f(c[j][0] + bo0);
        scr[(wid * 16 + g) * SCRP + col + 1]     = gelu_f(c[j][1] + bo1);
        scr[(wid * 16 + g + 8) * SCRP + col]     = gelu_f(c[j][2] + bo0);
        scr[(wid * 16 + g + 8) * SCRP + col + 1] = gelu_f(c[j][3] + bo1);
    }
    __syncthreads();
    {
        const int h = t >> 7;
        const int cc = t & 127;
        const int row_base = (is_sq ? mt : (mt - NSQT)) * 128;
        const float scale = is_sq ? (1.0f / 64.0f) : (1.0f / 24.0f);
        const int gr0 = row_base + h * 64;
        int cur = is_sq ? (gr0 >> 6) : (gr0 / 24);
        float acc = 0.f;
        #pragma unroll 4
        for (int rr = 0; rr < 64; rr++) {
            int gr = gr0 + rr;
            int nbd = is_sq ? (gr >> 6) : (gr / 24);
            if (nbd != cur) {
                atomicAdd(&g_shared[cur * DDIM + nh * 128 + cc], acc * scale);
                acc = 0.f; cur = nbd;
            }
            acc += scr[(h * 64 + rr) * SCRP + cc];
        }
        atomicAdd(&g_shared[cur * DDIM + nh * 128 + cc], acc * scale);
    }
}

// ============================================================================
// heads: 64 rows/CTA, grid 32
// ============================================================================
#define SMEM2_BYTES ((16384 + 32768) * 4)
__global__ void __launch_bounds__(256) heads_kernel(
    const float* __restrict__ W_pt, const float* __restrict__ b_pt,
    const float* __restrict__ W_vt, const float* __restrict__ b_vt)
{
    extern __shared__ float sm[];
    float* At = sm;
    float* Bt = sm + 16384;
    const int t = threadIdx.x;
    const int r0 = blockIdx.x * 64;
    for (int i = t; i < 64 * 256; i += 256) At[i] = g_shared[r0 * 256 + i];
    const int c4 = (t & 31) * 4;
    const int rg = t >> 5;
    #pragma unroll
    for (int w = 0; w < 2; w++) {
        __syncthreads();
        const float* W  = w ? W_vt : W_pt;
        const float* bb = w ? b_vt : b_pt;
        float* outp     = w ? g_vt : g_pt;
        for (int i = t; i < 256 * 128; i += 256) Bt[i] = W[i];
        __syncthreads();
        float C[8][4];
        #pragma unroll
        for (int i = 0; i < 8; i++)
            #pragma unroll
            for (int j = 0; j < 4; j++) C[i][j] = 0.f;
        #pragma unroll 2
        for (int k = 0; k < 256; k += 4) {
            float4 a[8];
            #pragma unroll
            for (int i = 0; i < 8; i++) a[i] = *(const float4*)&At[(rg * 8 + i) * 256 + k];
            #pragma unroll
            for (int kk = 0; kk < 4; kk++) {
                float4 bv = *(const float4*)&Bt[(k + kk) * 128 + c4];
                #pragma unroll
                for (int i = 0; i < 8; i++) {
                    float av = sel4(a[i], kk);
                    C[i][0] += av * bv.x; C[i][1] += av * bv.y;
                    C[i][2] += av * bv.z; C[i][3] += av * bv.w;
                }
            }
        }
        #pragma unroll
        for (int i = 0; i < 8; i++) {
            int r = r0 + rg * 8 + i;
            float4 o;
            o.x = gelu_f(C[i][0] + bb[c4 + 0]);
            o.y = gelu_f(C[i][1] + bb[c4 + 1]);
            o.z = gelu_f(C[i][2] + bb[c4 + 2]);
            o.w = gelu_f(C[i][3] + bb[c4 + 3]);
            *(float4*)&outp[r * 128 + c4] = o;
        }
    }
}

// ============================================================================
// policy: HMMA 3-pass, grid (37, 16)
// ============================================================================
__global__ void __launch_bounds__(256, 1) policy_kernel(
    const float* __restrict__ b_ph, float* __restrict__ out)
{
    extern __shared__ uint8_t smraw[];
    __nv_bfloat16* Ahi = (__nv_bfloat16*)(smraw);
    __nv_bfloat16* Alo = (__nv_bfloat16*)(smraw + TILEB);
    uint32_t* Bhi = (uint32_t*)(smraw + 2 * TILEB);
    uint32_t* Blo = (uint32_t*)(smraw + 2 * TILEB + BFRAGB);
    const int t = threadIdx.x;
    const int lane = t & 31, wid = t >> 5;
    const int g = lane >> 2, tg = lane & 3;
    const int nt = blockIdx.x;
    const int mtl = blockIdx.y;

    stage_Bfrag(Bhi, Blo, g_Wph + (size_t)nt * 32768, t);
    stage_Asrc(Ahi, Alo, g_pt + (size_t)mtl * 16384, t);
    __syncthreads();

    float c[16][4];
    #pragma unroll
    for (int j = 0; j < 16; j++)
        #pragma unroll
        for (int q = 0; q < 4; q++) c[j][q] = 0.f;
    mma_3pass(c, Ahi, Alo, Bhi, Blo, wid, g, tg, lane);

    #pragma unroll
    for (int j = 0; j < 16; j++) {
        int colg = nt * 128 + j * 8 + tg * 2;
        if (colg < ADIM) {
            float2 bp = *(const float2*)&b_ph[colg];
            int r0 = mtl * 128 + wid * 16 + g;
            *(float2*)&out[(size_t)r0 * ADIM + colg] =
                make_float2(c[j][0] + bp.x, c[j][1] + bp.y);
            *(float2*)&out[(size_t)(r0 + 8) * ADIM + colg] =
                make_float2(c[j][2] + bp.x, c[j][3] + bp.y);
        }
    }
}

__global__ void __launch_bounds__(256) value_kernel(
    const float* __restrict__ W_vh, const float* __restrict__ b_vh,
    float* __restrict__ out)
{
    int r = blockIdx.x * 8 + (threadIdx.x >> 5);
    int lane = threadIdx.x & 31;
    float acc = 0.f;
    #pragma unroll
    for (int q = 0; q < 4; q++)
        acc += g_vt[r * 128 + q * 32 + lane] * W_vh[q * 32 + lane];
    #pragma unroll
    for (int o = 16; o; o >>= 1) acc += __shfl_xor_sync(0xffffffffu, acc, o);
    if (lane == 0) out[(size_t)NB * ADIM + r] = tanhf(acc + b_vh[0]);
}

extern "C" void kernel_launch(void* const* d_in, const int* in_sizes, int n_in,
                              void* d_out, int out_size) {
    (void)in_sizes; (void)n_in; (void)out_size;
    const float* x_sq    = (const float*)d_in[0];
    const float* x_pc    = (const float*)d_in[1];
    const float* W_in_sq = (const float*)d_in[2];
    const float* b_in_sq = (const float*)d_in[3];
    const float* W_in_pc = (const float*)d_in[4];
    const float* b_in_pc = (const float*)d_in[5];
    const float* W_adj   = (const float*)d_in[6];
    const float* W_occ   = (const float*)d_in[7];
    const float* W_att   = (const float*)d_in[8];
    const float* W_def   = (const float*)d_in[9];
    const float* W_rev   = (const float*)d_in[10];
    const float* W_out   = (const float*)d_in[11];
    const float* b_out   = (const float*)d_in[12];
    const float* W_pt    = (const float*)d_in[13];
    const float* b_pt    = (const float*)d_in[14];
    const float* W_vt    = (const float*)d_in[15];
    const float* b_vt    = (const float*)d_in[16];
    const float* W_ph    = (const float*)d_in[17];
    const float* b_ph    = (const float*)d_in[18];
    const float* W_vh    = (const float*)d_in[19];
    const float* b_vh    = (const float*)d_in[20];
    const int* ei_adj    = (const int*)d_in[21];
    const int* ei_occ    = (const int*)d_in[22];
    const int* ei_att    = (const int*)d_in[23];
    const int* ei_def    = (const int*)d_in[24];
    const int* ei_rev    = (const int*)d_in[25];
    float* out = (float*)d_out;

    cudaFuncSetAttribute(stage1_kernel,  cudaFuncAttributeMaxDynamicSharedMemorySize, S1_BYTES);
    cudaFuncSetAttribute(gemmA_kernel,   cudaFuncAttributeMaxDynamicSharedMemorySize, TILE_SMEM);
    cudaFuncSetAttribute(outgemm_kernel, cudaFuncAttributeMaxDynamicSharedMemorySize, TILE_SMEM);
    cudaFuncSetAttribute(policy_kernel,  cudaFuncAttributeMaxDynamicSharedMemorySize, TILE_SMEM);
    cudaFuncSetAttribute(heads_kernel,   cudaFuncAttributeMaxDynamicSharedMemorySize, SMEM2_BYTES);

    prep_kernel<<<128, 256>>>(W_adj, W_occ, W_att, W_def, W_rev, W_out, W_ph);

    stage1_kernel<<<NB, T512, S1_BYTES>>>(
        x_sq, x_pc, W_in_sq, b_in_sq, W_in_pc, b_in_pc,
        ei_adj, ei_att, ei_def, ei_rev);

    gemmA_kernel<<<NSQT + 2 * NPCT, 256, TILE_SMEM>>>();

    stage2_kernel<<<NB, T512>>>(ei_occ);

    outgemm_kernel<<<(NSQT + NPCT) * 2, 256, TILE_SMEM>>>(b_out);

    heads_kernel<<<NB / 64, 256, SMEM2_BYTES>>>(W_pt, b_pt, W_vt, b_vt);

    policy_kernel<<<dim3(37, 16), 256, TILE_SMEM>>>(b_ph, out);

    value_kernel<<<NB / 8, 256>>>(W_vh, b_vh, out);
}

// round 17
// speedup vs baseline: 1.1536x; 1.1536x over previous
#include <cuda_runtime.h>
#include <cuda_bf16.h>
#include <math.h>
#include <stdint.h>

#define NB   2048
#define SQN  64
#define PCN  24
#define FDIM 16
#define HDIM 128
#define DDIM 256
#define TDIM 128
#define ADIM 4672
#define APAD 4736
#define E_ADJ 420
#define E_OCC 24
#define E_ATT 40
#define E_DEF 40
#define E_REV 24
#define T512 512
#define NSQT 1024
#define NPCT 384
#define PCSEC (NPCT * 16384)

__device__ float g_shared[NB * DDIM];
__device__ float g_pt[NB * TDIM];
__device__ float g_vt[NB * TDIM];
__device__ float g_hsq[NB * SQN * HDIM];
__device__ float g_rawsq[NB * SQN * HDIM];       // rawAdj -> aggsq -> h2sq
__device__ float g_hpc[NB * PCN * HDIM];
__device__ float g_rawpc[3 * NB * PCN * HDIM];   // att|def|rev raws; sec0 -> h2pc
__device__ float g_pocc[NB * PCN * HDIM];
__device__ __nv_bfloat16 g_Wimg[7 * 2 * 16384];  // adj,occ,att,def,rev,out0,out1 [hi|lo][n][k]
__device__ __nv_bfloat16 g_Wph[2 * APAD * 128];  // policy weights [hi|lo][n][k]

__device__ __forceinline__ float gelu_f(float x) {
    float u = 0.7978845608028654f * x + 0.0356774081f * x * x * x;
    float au = fabsf(u);
    float e = __expf(-2.0f * au);
    float t = __fdividef(1.0f - e, 1.0f + e);
    t = copysignf(t, u);
    return 0.5f * x * (1.0f + t);
}
__device__ __forceinline__ float sel4(float4 v, int kk) {
    return kk == 0 ? v.x : kk == 1 ? v.y : kk == 2 ? v.z : v.w;
}
__device__ __forceinline__ void mma_bf16(float c[4], uint32_t a0, uint32_t a1,
                                         uint32_t a2, uint32_t a3,
                                         uint32_t b0, uint32_t b1) {
    asm volatile(
        "mma.sync.aligned.m16n8k16.row.col.f32.bf16.bf16.f32 "
        "{%0,%1,%2,%3}, {%4,%5,%6,%7}, {%8,%9}, {%0,%1,%2,%3};"
        : "+f"(c[0]), "+f"(c[1]), "+f"(c[2]), "+f"(c[3])
        : "r"(a0), "r"(a1), "r"(a2), "r"(a3), "r"(b0), "r"(b1));
}

// ------------- HMMA tile machinery: K-halved staging, 2 CTAs/SM -------------
#define PADH 72
#define HTILEB (128 * PADH * 2)       /* 18432 B per bf16 half-tile */
#define TILE_SMEM (4 * HTILEB)        /* 73728 B -> 2 CTAs/SM */
#define SCRP 132

// stage K-half kh of a 128x128 bf16 image (row-major n*128+k); pure uint4 copy
__device__ __forceinline__ void stage_Bhalf(__nv_bfloat16* Bh, __nv_bfloat16* Bl,
                                            const __nv_bfloat16* srcHi,
                                            const __nv_bfloat16* srcLo,
                                            int kh, int t) {
    const uint4* sH = (const uint4*)srcHi;
    const uint4* sL = (const uint4*)srcLo;
    uint4* dH = (uint4*)Bh;
    uint4* dL = (uint4*)Bl;
    #pragma unroll
    for (int i = 0; i < 4; i++) {
        int e = t + i * 256;          // 0..1023
        int n = e >> 3, q = e & 7;
        int so = n * 16 + kh * 8 + q;
        int dо = n * 9 + q;           // PADH/8 = 9 uint4 per row
        dH[dо] = sH[so];
        dL[dо] = sL[so];
    }
}
// stage K-half kh of fp32 A (row-major r*128+k) as bf16 hi/lo
__device__ __forceinline__ void stage_Ahalf(__nv_bfloat16* Ahi, __nv_bfloat16* Alo,
                                            const float* __restrict__ Asrc,
                                            int kh, int t) {
    #pragma unroll
    for (int i = 0; i < 8; i++) {
        int e = t + i * 256;          // 0..2047 float4 granules
        int r = e >> 4, k0 = (e & 15) * 4;
        float4 v = *(const float4*)&Asrc[r * 128 + kh * 64 + k0];
        __nv_bfloat162 h0 = __floats2bfloat162_rn(v.x, v.y);
        __nv_bfloat162 h1 = __floats2bfloat162_rn(v.z, v.w);
        __nv_bfloat162 l0 = __floats2bfloat162_rn(v.x - __bfloat162float(h0.x),
                                                  v.y - __bfloat162float(h0.y));
        __nv_bfloat162 l1 = __floats2bfloat162_rn(v.z - __bfloat162float(h1.x),
                                                  v.w - __bfloat162float(h1.y));
        int o = r * PADH + k0;
        *(uint2*)&Ahi[o] = make_uint2(*(uint32_t*)&h0, *(uint32_t*)&h1);
        *(uint2*)&Alo[o] = make_uint2(*(uint32_t*)&l0, *(uint32_t*)&l1);
    }
}
// 3-pass hi/lo mma over one K-half (kk = 0..3)
__device__ __forceinline__ void mma_3pass_h(float c[16][4],
                                            const __nv_bfloat16* Ahi, const __nv_bfloat16* Alo,
                                            const __nv_bfloat16* Bhi, const __nv_bfloat16* Blo,
                                            int wid, int g, int tg) {
    const int ra = wid * 16 + g;
    #pragma unroll
    for (int p = 0; p < 3; p++) {
        const __nv_bfloat16* As = (p == 2) ? Alo : Ahi;
        const __nv_bfloat16* Bs = (p == 1) ? Blo : Bhi;
        #pragma unroll
        for (int kk = 0; kk < 4; kk++) {
            const int kb = kk * 16 + tg * 2;
            uint32_t a0 = *(const uint32_t*)&As[ra * PADH + kb];
            uint32_t a1 = *(const uint32_t*)&As[(ra + 8) * PADH + kb];
            uint32_t a2 = *(const uint32_t*)&As[ra * PADH + kb + 8];
            uint32_t a3 = *(const uint32_t*)&As[(ra + 8) * PADH + kb + 8];
            #pragma unroll
            for (int j = 0; j < 16; j++) {
                const int nb = j * 8 + g;
                uint32_t b0 = *(const uint32_t*)&Bs[nb * PADH + kb];
                uint32_t b1 = *(const uint32_t*)&Bs[nb * PADH + kb + 8];
                mma_bf16(c[j], a0, a1, a2, a3, b0, b1);
            }
        }
    }
}
// full tile = two staged K-halves, accumulating into c
__device__ __forceinline__ void tile_gemm(float c[16][4],
                                          __nv_bfloat16* Ahi, __nv_bfloat16* Alo,
                                          __nv_bfloat16* Bhi, __nv_bfloat16* Blo,
                                          const float* Asrc,
                                          const __nv_bfloat16* BsrcHi,
                                          const __nv_bfloat16* BsrcLo,
                                          int wid, int g, int tg, int t) {
    #pragma unroll
    for (int kh = 0; kh < 2; kh++) {
        __syncthreads();
        stage_Bhalf(Bhi, Blo, BsrcHi, BsrcLo, kh, t);
        stage_Ahalf(Ahi, Alo, Asrc, kh, t);
        __syncthreads();
        mma_3pass_h(c, Ahi, Alo, Bhi, Blo, wid, g, tg);
    }
}

// ============================================================================
__global__ void __launch_bounds__(256) prep_kernel(
    const float* __restrict__ W_adj, const float* __restrict__ W_occ,
    const float* __restrict__ W_att, const float* __restrict__ W_def,
    const float* __restrict__ W_rev, const float* __restrict__ W_out,
    const float* __restrict__ W_ph)
{
    const float* Ws[5] = {W_adj, W_occ, W_att, W_def, W_rev};
    int tid = blockIdx.x * 256 + threadIdx.x;
    int stride = gridDim.x * 256;
    for (int i = tid; i < NB * DDIM; i += stride) g_shared[i] = 0.f;
    for (int i = tid; i < 7 * 16384; i += stride) {
        int idx = i >> 14, n = (i >> 7) & 127, k = i & 127;
        float v = (idx < 5) ? Ws[idx][k * 128 + n] : W_out[k * 256 + (idx - 5) * 128 + n];
        __nv_bfloat16 hi = __float2bfloat16(v);
        __nv_bfloat16 lo = __float2bfloat16(v - __bfloat162float(hi));
        g_Wimg[idx * 32768 + n * 128 + k] = hi;
        g_Wimg[idx * 32768 + 16384 + n * 128 + k] = lo;
    }
    for (int i = tid; i < APAD * 128; i += stride) {
        int n = i >> 7, k = i & 127;
        float v = (n < ADIM) ? W_ph[k * ADIM + n] : 0.f;
        __nv_bfloat16 hi = __float2bfloat16(v);
        __nv_bfloat16 lo = __float2bfloat16(v - __bfloat162float(hi));
        g_Wph[n * 128 + k] = hi;
        g_Wph[APAD * 128 + n * 128 + k] = lo;
    }
}

// ============================================================================
// stage1: per board — input GEMM + gelu + edge aggregation
// ============================================================================
#define S1_HSQ  0
#define S1_HPC  8192
#define S1_RADJ 11264
#define S1_RATT 19456
#define S1_RDEF 22528
#define S1_RREV 25600
#define S1_XS   28672
#define S1_XP   29696
#define S1_WI1  30080
#define S1_WI2  32128
#define S1_EIDX 34176
#define S1_BYTES ((34176 + 524) * 4)

__global__ void __launch_bounds__(T512, 1) stage1_kernel(
    const float* __restrict__ x_sq, const float* __restrict__ x_pc,
    const float* __restrict__ W_in_sq, const float* __restrict__ b_in_sq,
    const float* __restrict__ W_in_pc, const float* __restrict__ b_in_pc,
    const int* __restrict__ ei_adj, const int* __restrict__ ei_att,
    const int* __restrict__ ei_def, const int* __restrict__ ei_rev)
{
    extern __shared__ float sm[];
    float* h_sq = sm + S1_HSQ;
    float* h_pc = sm + S1_HPC;
    float* rawAdj = sm + S1_RADJ;
    float* rawAtt = sm + S1_RATT;
    float* rawDef = sm + S1_RDEF;
    float* rawRev = sm + S1_RREV;
    int* eidx = (int*)(sm + S1_EIDX);
    const int b = blockIdx.x;
    const int t = threadIdx.x;

    {
        const int ba = b * E_ADJ;
        for (int i = t; i < E_ADJ; i += T512) {
            int s = ei_adj[ba + i] - b * SQN;
            int d = ei_adj[NB * E_ADJ + ba + i] - b * SQN;
            eidx[i] = s | (d << 8);
        }
        const int bt = b * E_ATT;
        for (int i = t; i < E_ATT; i += T512) {
            int s = ei_att[bt + i] - b * PCN;
            int d = ei_att[NB * E_ATT + bt + i] - b * PCN;
            eidx[E_ADJ + i] = s | (d << 8);
            int s2 = ei_def[bt + i] - b * PCN;
            int d2 = ei_def[NB * E_DEF + bt + i] - b * PCN;
            eidx[E_ADJ + E_ATT + i] = s2 | (d2 << 8);
        }
        const int bo = b * E_REV;
        for (int i = t; i < E_REV; i += T512) {
            int s = ei_rev[bo + i] - b * SQN;
            int d = ei_rev[NB * E_REV + bo + i] - b * PCN;
            eidx[500 + i] = s | (d << 8);
        }
    }
    {
        float4* r4 = (float4*)rawAdj;
        for (int i = t; i < 4352; i += T512) r4[i] = make_float4(0.f, 0.f, 0.f, 0.f);
    }
    {
        float* xs = sm + S1_XS; float* xp = sm + S1_XP;
        float* wi1 = sm + S1_WI1; float* wi2 = sm + S1_WI2;
        for (int i = t; i < SQN * FDIM; i += T512) xs[i] = x_sq[b * SQN * FDIM + i];
        for (int i = t; i < PCN * FDIM; i += T512) xp[i] = x_pc[b * PCN * FDIM + i];
        for (int i = t; i < FDIM * HDIM; i += T512) { wi1[i] = W_in_sq[i]; wi2[i] = W_in_pc[i]; }
    }
    __syncthreads();
    {
        const float* xs = sm + S1_XS; const float* xp = sm + S1_XP;
        const float* wi1 = sm + S1_WI1; const float* wi2 = sm + S1_WI2;
        const int c = t & 127, q = t >> 7;
        float wcol[16];
        #pragma unroll
        for (int k = 0; k < 16; k++) wcol[k] = wi1[k * 128 + c];
        float bias = b_in_sq[c];
        for (int r = q * 16; r < q * 16 + 16; r++) {
            float acc = bias;
            #pragma unroll
            for (int k = 0; k < 16; k++) acc += xs[r * 16 + k] * wcol[k];
            h_sq[r * 128 + c] = gelu_f(acc);
        }
        #pragma unroll
        for (int k = 0; k < 16; k++) wcol[k] = wi2[k * 128 + c];
        bias = b_in_pc[c];
        for (int r = q * 6; r < q * 6 + 6; r++) {
            float acc = bias;
            #pragma unroll
            for (int k = 0; k < 16; k++) acc += xp[r * 16 + k] * wcol[k];
            h_pc[r * 128 + c] = gelu_f(acc);
        }
    }
    __syncthreads();
    {
        const int g = t >> 7, c = t & 127;
        for (int i = g; i < E_ADJ; i += 4) {
            int e = eidx[i];
            atomicAdd(&rawAdj[(e >> 8) * 128 + c], h_sq[(e & 255) * 128 + c]);
        }
        for (int i = g; i < E_ATT; i += 4) {
            int e = eidx[E_ADJ + i];
            atomicAdd(&rawAtt[(e >> 8) * 128 + c], h_pc[(e & 255) * 128 + c]);
        }
        for (int i = g; i < E_DEF; i += 4) {
            int e = eidx[E_ADJ + E_ATT + i];
            atomicAdd(&rawDef[(e >> 8) * 128 + c], h_pc[(e & 255) * 128 + c]);
        }
        for (int i = g; i < E_REV; i += 4) {
            int e = eidx[500 + i];
            atomicAdd(&rawRev[(e >> 8) * 128 + c], h_sq[(e & 255) * 128 + c]);
        }
    }
    __syncthreads();
    {
        float4* d1 = (float4*)(g_hsq + (size_t)b * 8192);
        float4* d2 = (float4*)(g_rawsq + (size_t)b * 8192);
        const float4* s1 = (const float4*)h_sq;
        const float4* s2 = (const float4*)rawAdj;
        #pragma unroll
        for (int i = 0; i < 4; i++) { d1[t + i * T512] = s1[t + i * T512]; d2[t + i * T512] = s2[t + i * T512]; }
        float4* dh = (float4*)(g_hpc + (size_t)b * 3072);
        const float4* sh = (const float4*)h_pc;
        float4* da = (float4*)(g_rawpc + (size_t)b * 3072);
        float4* dd = (float4*)(g_rawpc + (size_t)PCSEC + (size_t)b * 3072);
        float4* dr = (float4*)(g_rawpc + (size_t)2 * PCSEC + (size_t)b * 3072);
        const float4* sa = (const float4*)rawAtt;
        const float4* sd = (const float4*)rawDef;
        const float4* sr = (const float4*)rawRev;
        for (int i = t; i < 768; i += T512) { dh[i] = sh[i]; da[i] = sa[i]; dd[i] = sd[i]; dr[i] = sr[i]; }
    }
}

// ============================================================================
// gemmA: pc-agg (fused h2pc epilogue) first, then pocc, then sq-agg
// ============================================================================
__global__ void __launch_bounds__(256, 2) gemmA_kernel() {
    extern __shared__ uint8_t smraw[];
    __nv_bfloat16* Ahi = (__nv_bfloat16*)(smraw);
    __nv_bfloat16* Alo = (__nv_bfloat16*)(smraw + HTILEB);
    __nv_bfloat16* Bhi = (__nv_bfloat16*)(smraw + 2 * HTILEB);
    __nv_bfloat16* Blo = (__nv_bfloat16*)(smraw + 3 * HTILEB);
    const int t = threadIdx.x;
    const int lane = t & 31, wid = t >> 5;
    const int g = lane >> 2, tg = lane & 3;
    const int bx = blockIdx.x;

    float c[16][4];
    #pragma unroll
    for (int j = 0; j < 16; j++)
        #pragma unroll
        for (int q = 0; q < 4; q++) c[j][q] = 0.f;

    if (bx < NPCT) {
        const int mt = bx;
        #pragma unroll
        for (int s = 0; s < 3; s++) {
            tile_gemm(c, Ahi, Alo, Bhi, Blo,
                      g_rawpc + (size_t)s * PCSEC + (size_t)mt * 16384,
                      g_Wimg + (2 + s) * 32768, g_Wimg + (2 + s) * 32768 + 16384,
                      wid, g, tg, t);
        }
        float* out = g_rawpc + (size_t)mt * 16384;
        const float* hp = g_hpc + (size_t)mt * 16384;
        __syncthreads();
        #pragma unroll
        for (int j = 0; j < 16; j++) {
            int col = j * 8 + tg * 2;
            int r0 = wid * 16 + g;
            float2 h0 = *(const float2*)&hp[r0 * 128 + col];
            float2 h1 = *(const float2*)&hp[(r0 + 8) * 128 + col];
            *(float2*)&out[r0 * 128 + col] =
                make_float2(gelu_f(h0.x + c[j][0]), gelu_f(h0.y + c[j][1]));
            *(float2*)&out[(r0 + 8) * 128 + col] =
                make_float2(gelu_f(h1.x + c[j][2]), gelu_f(h1.y + c[j][3]));
        }
    } else {
        float* out;
        if (bx < 2 * NPCT) {
            const int mt = bx - NPCT;
            tile_gemm(c, Ahi, Alo, Bhi, Blo, g_hpc + (size_t)mt * 16384,
                      g_Wimg + 32768, g_Wimg + 32768 + 16384, wid, g, tg, t);
            out = g_pocc + (size_t)mt * 16384;
        } else {
            const int mt = bx - 2 * NPCT;
            tile_gemm(c, Ahi, Alo, Bhi, Blo, g_rawsq + (size_t)mt * 16384,
                      g_Wimg, g_Wimg + 16384, wid, g, tg, t);
            out = g_rawsq + (size_t)(bx - 2 * NPCT) * 16384;
        }
        __syncthreads();
        #pragma unroll
        for (int j = 0; j < 16; j++) {
            int col = j * 8 + tg * 2;
            int r0 = wid * 16 + g;
            *(float2*)&out[r0 * 128 + col] = make_float2(c[j][0], c[j][1]);
            *(float2*)&out[(r0 + 8) * 128 + col] = make_float2(c[j][2], c[j][3]);
        }
    }
}

// ============================================================================
// stage2: sq only — agg = rawsq + occ-scatter(pocc); h2sq = gelu(hsq+agg)
// ============================================================================
__global__ void __launch_bounds__(T512) stage2_kernel(const int* __restrict__ ei_occ) {
    __shared__ float agg[SQN * HDIM];
    const int b = blockIdx.x;
    const int t = threadIdx.x;
    float4* a4 = (float4*)agg;
    const float4* s4 = (const float4*)(g_rawsq + (size_t)b * 8192);
    #pragma unroll
    for (int i = 0; i < 4; i++) a4[t + i * T512] = s4[t + i * T512];
    __syncthreads();
    {
        const int g = t >> 7, c = t & 127;
        for (int i = g; i < E_OCC; i += 4) {
            int sp = ei_occ[b * E_OCC + i] - b * PCN;
            int d  = ei_occ[NB * E_OCC + b * E_OCC + i] - b * SQN;
            atomicAdd(&agg[d * 128 + c], g_pocc[((size_t)b * PCN + sp) * 128 + c]);
        }
    }
    __syncthreads();
    const float4* h4 = (const float4*)(g_hsq + (size_t)b * 8192);
    float4* o4 = (float4*)(g_rawsq + (size_t)b * 8192);
    #pragma unroll
    for (int i = 0; i < 4; i++) {
        int idx = t + i * T512;
        float4 h = h4[idx];
        float4 a = a4[idx];
        float4 o;
        o.x = gelu_f(h.x + a.x); o.y = gelu_f(h.y + a.y);
        o.z = gelu_f(h.z + a.z); o.w = gelu_f(h.w + a.w);
        o4[idx] = o;
    }
}

// ============================================================================
// outgemm: D = h2 @ W_out[nh]; parallel board-mean epilogue
// ============================================================================
__global__ void __launch_bounds__(256, 2) outgemm_kernel(const float* __restrict__ b_out) {
    extern __shared__ uint8_t smraw[];
    __nv_bfloat16* Ahi = (__nv_bfloat16*)(smraw);
    __nv_bfloat16* Alo = (__nv_bfloat16*)(smraw + HTILEB);
    __nv_bfloat16* Bhi = (__nv_bfloat16*)(smraw + 2 * HTILEB);
    __nv_bfloat16* Blo = (__nv_bfloat16*)(smraw + 3 * HTILEB);
    const int t = threadIdx.x;
    const int lane = t & 31, wid = t >> 5;
    const int g = lane >> 2, tg = lane & 3;
    const int mt = blockIdx.x >> 1;
    const int nh = blockIdx.x & 1;
    const bool is_sq = mt < NSQT;
    const float* Asrc = is_sq ? (g_rawsq + (size_t)mt * 16384)
                              : (g_rawpc + (size_t)(mt - NSQT) * 16384);

    float c[16][4];
    #pragma unroll
    for (int j = 0; j < 16; j++)
        #pragma unroll
        for (int q = 0; q < 4; q++) c[j][q] = 0.f;

    tile_gemm(c, Ahi, Alo, Bhi, Blo, Asrc,
              g_Wimg + (5 + nh) * 32768, g_Wimg + (5 + nh) * 32768 + 16384,
              wid, g, tg, t);
    __syncthreads();

    float* scr = (float*)smraw;
    #pragma unroll
    for (int j = 0; j < 16; j++) {
        int col = j * 8 + tg * 2;
        float bo0 = b_out[nh * 128 + col];
        float bo1 = b_out[nh * 128 + col + 1];
        scr[(wid * 16 + g) * SCRP + col]         = gelu_f(c[j][0] + bo0);
        scr[(wid * 16 + g) * SCRP + col + 1]     = gelu_f(c[j][1] + bo1);
        scr[(wid * 16 + g + 8) * SCRP + col]     = gelu_f(c[j][2] + bo0);
        scr[(wid * 16 + g + 8) * SCRP + col + 1] = gelu_f(c[j][3] + bo1);
    }
    __syncthreads();
    {
        const int h = t >> 7;
        const int cc = t & 127;
        const int row_base = (is_sq ? mt : (mt - NSQT)) * 128;
        const float scale = is_sq ? (1.0f / 64.0f) : (1.0f / 24.0f);
        const int gr0 = row_base + h * 64;
        int cur = is_sq ? (gr0 >> 6) : (gr0 / 24);
        float acc = 0.f;
        #pragma unroll 4
        for (int rr = 0; rr < 64; rr++) {
            int gr = gr0 + rr;
            int nbd = is_sq ? (gr >> 6) : (gr / 24);
            if (nbd != cur) {
                atomicAdd(&g_shared[cur * DDIM + nh * 128 + cc], acc * scale);
                acc = 0.f; cur = nbd;
            }
            acc += scr[(h * 64 + rr) * SCRP + cc];
        }
        atomicAdd(&g_shared[cur * DDIM + nh * 128 + cc], acc * scale);
    }
}

// ============================================================================
// heads: 64 rows/CTA, grid 32
// ============================================================================
#define SMEM2_BYTES ((16384 + 32768) * 4)
__global__ void __launch_bounds__(256) heads_kernel(
    const float* __restrict__ W_pt, const float* __restrict__ b_pt,
    const float* __restrict__ W_vt, const float* __restrict__ b_vt)
{
    extern __shared__ float sm[];
    float* At = sm;
    float* Bt = sm + 16384;
    const int t = threadIdx.x;
    const int r0 = blockIdx.x * 64;
    for (int i = t; i < 64 * 256; i += 256) At[i] = g_shared[r0 * 256 + i];
    const int c4 = (t & 31) * 4;
    const int rg = t >> 5;
    #pragma unroll
    for (int w = 0; w < 2; w++) {
        __syncthreads();
        const float* W  = w ? W_vt : W_pt;
        const float* bb = w ? b_vt : b_pt;
        float* outp     = w ? g_vt : g_pt;
        for (int i = t; i < 256 * 128; i += 256) Bt[i] = W[i];
        __syncthreads();
        float C[8][4];
        #pragma unroll
        for (int i = 0; i < 8; i++)
            #pragma unroll
            for (int j = 0; j < 4; j++) C[i][j] = 0.f;
        #pragma unroll 2
        for (int k = 0; k < 256; k += 4) {
            float4 a[8];
            #pragma unroll
            for (int i = 0; i < 8; i++) a[i] = *(const float4*)&At[(rg * 8 + i) * 256 + k];
            #pragma unroll
            for (int kk = 0; kk < 4; kk++) {
                float4 bv = *(const float4*)&Bt[(k + kk) * 128 + c4];
                #pragma unroll
                for (int i = 0; i < 8; i++) {
                    float av = sel4(a[i], kk);
                    C[i][0] += av * bv.x; C[i][1] += av * bv.y;
                    C[i][2] += av * bv.z; C[i][3] += av * bv.w;
                }
            }
        }
        #pragma unroll
        for (int i = 0; i < 8; i++) {
            int r = r0 + rg * 8 + i;
            float4 o;
            o.x = gelu_f(C[i][0] + bb[c4 + 0]);
            o.y = gelu_f(C[i][1] + bb[c4 + 1]);
            o.z = gelu_f(C[i][2] + bb[c4 + 2]);
            o.w = gelu_f(C[i][3] + bb[c4 + 3]);
            *(float4*)&outp[r * 128 + c4] = o;
        }
    }
}

// ============================================================================
// policy: HMMA 3-pass K-halved, grid (37, 16)
// ============================================================================
__global__ void __launch_bounds__(256, 2) policy_kernel(
    const float* __restrict__ b_ph, float* __restrict__ out)
{
    extern __shared__ uint8_t smraw[];
    __nv_bfloat16* Ahi = (__nv_bfloat16*)(smraw);
    __nv_bfloat16* Alo = (__nv_bfloat16*)(smraw + HTILEB);
    __nv_bfloat16* Bhi = (__nv_bfloat16*)(smraw + 2 * HTILEB);
    __nv_bfloat16* Blo = (__nv_bfloat16*)(smraw + 3 * HTILEB);
    const int t = threadIdx.x;
    const int lane = t & 31, wid = t >> 5;
    const int g = lane >> 2, tg = lane & 3;
    const int nt = blockIdx.x;
    const int mtl = blockIdx.y;

    float c[16][4];
    #pragma unroll
    for (int j = 0; j < 16; j++)
        #pragma unroll
        for (int q = 0; q < 4; q++) c[j][q] = 0.f;

    tile_gemm(c, Ahi, Alo, Bhi, Blo, g_pt + (size_t)mtl * 16384,
              g_Wph + (size_t)nt * 16384,
              g_Wph + (size_t)APAD * 128 + (size_t)nt * 16384,
              wid, g, tg, t);

    #pragma unroll
    for (int j = 0; j < 16; j++) {
        int colg = nt * 128 + j * 8 + tg * 2;
        if (colg < ADIM) {
            float2 bp = *(const float2*)&b_ph[colg];
            int r0 = mtl * 128 + wid * 16 + g;
            *(float2*)&out[(size_t)r0 * ADIM + colg] =
                make_float2(c[j][0] + bp.x, c[j][1] + bp.y);
            *(float2*)&out[(size_t)(r0 + 8) * ADIM + colg] =
                make_float2(c[j][2] + bp.x, c[j][3] + bp.y);
        }
    }
}

__global__ void __launch_bounds__(256) value_kernel(
    const float* __restrict__ W_vh, const float* __restrict__ b_vh,
    float* __restrict__ out)
{
    int r = blockIdx.x * 8 + (threadIdx.x >> 5);
    int lane = threadIdx.x & 31;
    float acc = 0.f;
    #pragma unroll
    for (int q = 0; q < 4; q++)
        acc += g_vt[r * 128 + q * 32 + lane] * W_vh[q * 32 + lane];
    #pragma unroll
    for (int o = 16; o; o >>= 1) acc += __shfl_xor_sync(0xffffffffu, acc, o);
    if (lane == 0) out[(size_t)NB * ADIM + r] = tanhf(acc + b_vh[0]);
}

extern "C" void kernel_launch(void* const* d_in, const int* in_sizes, int n_in,
                              void* d_out, int out_size) {
    (void)in_sizes; (void)n_in; (void)out_size;
    const float* x_sq    = (const float*)d_in[0];
    const float* x_pc    = (const float*)d_in[1];
    const float* W_in_sq = (const float*)d_in[2];
    const float* b_in_sq = (const float*)d_in[3];
    const float* W_in_pc = (const float*)d_in[4];
    const float* b_in_pc = (const float*)d_in[5];
    const float* W_adj   = (const float*)d_in[6];
    const float* W_occ   = (const float*)d_in[7];
    const float* W_att   = (const float*)d_in[8];
    const float* W_def   = (const float*)d_in[9];
    const float* W_rev   = (const float*)d_in[10];
    const float* W_out   = (const float*)d_in[11];
    const float* b_out   = (const float*)d_in[12];
    const float* W_pt    = (const float*)d_in[13];
    const float* b_pt    = (const float*)d_in[14];
    const float* W_vt    = (const float*)d_in[15];
    const float* b_vt    = (const float*)d_in[16];
    const float* W_ph    = (const float*)d_in[17];
    const float* b_ph    = (const float*)d_in[18];
    const float* W_vh    = (const float*)d_in[19];
    const float* b_vh    = (const float*)d_in[20];
    const int* ei_adj    = (const int*)d_in[21];
    const int* ei_occ    = (const int*)d_in[22];
    const int* ei_att    = (const int*)d_in[23];
    const int* ei_def    = (const int*)d_in[24];
    const int* ei_rev    = (const int*)d_in[25];
    float* out = (float*)d_out;

    cudaFuncSetAttribute(stage1_kernel,  cudaFuncAttributeMaxDynamicSharedMemorySize, S1_BYTES);
    cudaFuncSetAttribute(gemmA_kernel,   cudaFuncAttributeMaxDynamicSharedMemorySize, TILE_SMEM);
    cudaFuncSetAttribute(outgemm_kernel, cudaFuncAttributeMaxDynamicSharedMemorySize, TILE_SMEM);
    cudaFuncSetAttribute(policy_kernel,  cudaFuncAttributeMaxDynamicSharedMemorySize, TILE_SMEM);
    cudaFuncSetAttribute(heads_kernel,   cudaFuncAttributeMaxDynamicSharedMemorySize, SMEM2_BYTES);

    prep_kernel<<<128, 256>>>(W_adj, W_occ, W_att, W_def, W_rev, W_out, W_ph);

    stage1_kernel<<<NB, T512, S1_BYTES>>>(
        x_sq, x_pc, W_in_sq, b_in_sq, W_in_pc, b_in_pc,
        ei_adj, ei_att, ei_def, ei_rev);

    gemmA_kernel<<<NSQT + 2 * NPCT, 256, TILE_SMEM>>>();

    stage2_kernel<<<NB, T512>>>(ei_occ);

    outgemm_kernel<<<(NSQT + NPCT) * 2, 256, TILE_SMEM>>>(b_out);

    heads_kernel<<<NB / 64, 256, SMEM2_BYTES>>>(W_pt, b_pt, W_vt, b_vt);

    policy_kernel<<<dim3(37, 16), 256, TILE_SMEM>>>(b_ph, out);

    value_kernel<<<NB / 8, 256>>>(W_vh, b_vh, out);
}